// round 3
// baseline (speedup 1.0000x reference)
#include <cuda_runtime.h>
#include <math.h>

#define TCNT 4
#define CH 3
#define HH 128
#define WW 128
#define PSZ 5
#define KSEL 14
#define WSZ 29
#define WHALF 14
#define PADT 16
#define XPH 160
#define XPW 160
#define TX 32
#define TY 8
#define NOFF (WSZ*WSZ)
#define DFEAT 75
#define PLANE (TCNT*HH*WW)

// ---------------- device scratch (no allocations allowed) ----------------
__device__ float  g_mean[TCNT*CH];
__device__ float  g_beta;
__device__ float4 g_xp[TCNT*XPH*XPW];          // normalized, mean-sub, reflect-padded; c in .x/.y/.z
__device__ float  g_pdeno[DFEAT*PLANE];        // plane-major [d][t][H][W]
__device__ unsigned short g_ord[NOFF];         // ring-ordered offsets: (oy<<5)|ox

__device__ __forceinline__ unsigned long long u64min(unsigned long long a, unsigned long long b){return a<b?a:b;}
__device__ __forceinline__ unsigned long long u64max(unsigned long long a, unsigned long long b){return a>b?a:b;}

// ---------------- per (t,c) mean + beta ----------------
__global__ void k_means(const float* __restrict__ noisy, const int* __restrict__ sigp) {
    if (blockIdx.x == 0 && threadIdx.x == 0) {
        unsigned bits = *(const unsigned*)sigp;
        float sv = (bits >> 23) ? __uint_as_float(bits) : (float)(int)bits;
        float sig = sv / 127.5f;
        g_beta = 1.0f / (2.0f * sig * sig * (float)DFEAT);
    }
    int b = blockIdx.x;   // t*3+c
    const float* p = noisy + (size_t)b * (HH*WW);
    float s = 0.f;
    for (int i = threadIdx.x; i < HH*WW; i += 256) s += p[i];
    __shared__ float sm[8];
    #pragma unroll
    for (int off = 16; off; off >>= 1) s += __shfl_down_sync(0xffffffffu, s, off);
    if ((threadIdx.x & 31) == 0) sm[threadIdx.x >> 5] = s;
    __syncthreads();
    if (threadIdx.x == 0) {
        float tot = 0.f;
        #pragma unroll
        for (int i = 0; i < 8; i++) tot += sm[i];
        g_mean[b] = tot * (1.0f/(HH*WW)) * (1.0f/127.5f) - 1.0f;
    }
}

// ---------------- build padded normalized image (float4 per pixel) ----------------
__global__ void k_xp(const float* __restrict__ noisy) {
    int idx = blockIdx.x * 256 + threadIdx.x;       // over t*XPH*XPW
    if (idx >= TCNT*XPH*XPW) return;
    int ix = idx % XPW;
    int r  = idx / XPW;
    int iy = r % XPH;
    int t  = r / XPH;
    int jy = iy - PADT; jy = jy < 0 ? -jy : (jy > HH-1 ? 2*(HH-1)-jy : jy);
    int jx = ix - PADT; jx = jx < 0 ? -jx : (jx > WW-1 ? 2*(WW-1)-jx : jx);
    const float* base = noisy + (size_t)t * CH * HH * WW;
    float4 v;
    v.x = base[(size_t)(0*HH+jy)*WW + jx] * (1.f/127.5f) - 1.f - g_mean[t*3+0];
    v.y = base[(size_t)(1*HH+jy)*WW + jx] * (1.f/127.5f) - 1.f - g_mean[t*3+1];
    v.z = base[(size_t)(2*HH+jy)*WW + jx] * (1.f/127.5f) - 1.f - g_mean[t*3+2];
    v.w = 0.f;
    g_xp[idx] = v;
}

// ---------------- ring-order the 841 offsets (center outward) ----------------
__global__ void k_ord() {
    int o = blockIdx.x * blockDim.x + threadIdx.x;
    if (o >= NOFF) return;
    int oy = o / WSZ, ox = o - (o/WSZ)*WSZ;
    int dy = oy - WHALF, dx = ox - WHALF;
    int ady = dy < 0 ? -dy : dy, adx = dx < 0 ? -dx : dx;
    int rr = ady > adx ? ady : adx;
    int before = (rr == 0) ? 0 : (2*rr-1)*(2*rr-1);
    int cnt = 0;
    for (int yy = WHALF - rr; yy < oy; yy++) {
        int a = yy - WHALF; a = a < 0 ? -a : a;
        cnt += (a == rr) ? (2*rr + 1) : 2;
    }
    if (ady == rr) cnt += dx + rr;            // full row: columns before ox
    else          cnt += (dx == rr) ? 1 : 0;  // partial row: only +/- rr columns
    g_ord[before + cnt] = (unsigned short)((oy << 5) | ox);
}

// ---------------- main: distances + top-K + softmax + patch gather ----------------
__global__ void __launch_bounds__(256, 2) k_main() {
    __shared__ float4   reg4[40*64];      // 40KB region
    __shared__ float    e_sm[2][12*36];   // double-buffered squared-diff plane
    __shared__ unsigned ord_sm[NOFF];     // (off_lin<<16) | raster

    int t   = blockIdx.z;
    int ty0 = blockIdx.y * TY;
    int tx0 = blockIdx.x * TX;
    int tid = threadIdx.x;

    // stage region + offset table
    const float4* xp = g_xp + (size_t)t * XPH * XPW;
    #pragma unroll
    for (int i = tid; i < 40*64; i += 256) {
        int r = i >> 6, c = i & 63;
        reg4[i] = xp[(size_t)(ty0 + r) * XPW + tx0 + c];
    }
    for (int i = tid; i < NOFF; i += 256) {
        unsigned p  = g_ord[i];
        unsigned oy = p >> 5, ox = p & 31u;
        ord_sm[i] = ((oy * 64u + ox) << 16) | (oy * (unsigned)WSZ + ox);
    }
    __syncthreads();

    // register-cached query pixels for the e-plane (slots tid and tid+256)
    int er1 = tid / 36, ec1 = tid - er1 * 36;
    int it2 = tid + 256;
    int er2 = it2 / 36, ec2 = it2 - er2 * 36;       // valid when tid < 176
    float4 q1 = reg4[(er1 + 14) * 64 + (ec1 + 14)];
    float4 q2 = (tid < 176) ? reg4[(er2 + 14) * 64 + (ec2 + 14)] : make_float4(0.f,0.f,0.f,0.f);
    int nb1 = er1 * 64 + ec1;
    int nb2 = er2 * 64 + ec2;

    int ly = tid >> 5, l = tid & 31;

    unsigned long long keys[KSEL];
    #pragma unroll
    for (int i = 0; i < KSEL; i++) keys[i] = 0xFFFFFFFFFFFFFFFFULL;

    // prologue: phase A for offset 0 into buffer 0
    {
        int off_lin = (int)(ord_sm[0] >> 16);
        float4 n = reg4[nb1 + off_lin];
        float a = q1.x - n.x, b = q1.y - n.y, c = q1.z - n.z;
        e_sm[0][tid] = a*a + b*b + c*c;
        if (tid < 176) {
            float4 n2 = reg4[nb2 + off_lin];
            float a2 = q2.x - n2.x, b2 = q2.y - n2.y, c2 = q2.z - n2.z;
            e_sm[0][it2] = a2*a2 + b2*b2 + c2*c2;
        }
    }

    int buf = 0;
    for (int i = 0; i < NOFF; i++) {
        __syncthreads();
        unsigned cur = ord_sm[i];

        // phase A for next offset into the other buffer (pipelined)
        if (i + 1 < NOFF) {
            int off_lin = (int)(ord_sm[i + 1] >> 16);
            float* eb = e_sm[buf ^ 1];
            float4 n = reg4[nb1 + off_lin];
            float a = q1.x - n.x, b = q1.y - n.y, c = q1.z - n.z;
            eb[tid] = a*a + b*b + c*c;
            if (tid < 176) {
                float4 n2 = reg4[nb2 + off_lin];
                float a2 = q2.x - n2.x, b2 = q2.y - n2.y, c2 = q2.z - n2.z;
                eb[it2] = a2*a2 + b2*b2 + c2*c2;
            }
        }

        // fused vertical 5-sum + shuffle horizontal 5-sum + top-K insert
        {
            const float* r0 = e_sm[buf] + ly * 36;
            float v_a = r0[l]       + r0[36 + l]   + r0[72 + l]
                      + r0[108 + l] + r0[144 + l];
            int c2 = 32 + (l & 3);
            float v_b = r0[c2]       + r0[36 + c2]  + r0[72 + c2]
                      + r0[108 + c2] + r0[144 + c2];
            float d = v_a;
            #pragma unroll
            for (int k = 1; k <= 4; k++) {
                int src = (l + k) & 31;
                float av = __shfl_sync(0xffffffffu, v_a, src);
                float bv = __shfl_sync(0xffffffffu, v_b, src);
                d += (l + k < 32) ? av : bv;
            }
            unsigned long long key =
                ((unsigned long long)__float_as_uint(d) << 32) | (cur & 0xFFFFu);
            if (__any_sync(0xffffffffu, key < keys[KSEL-1])) {
                #pragma unroll
                for (int s = KSEL-1; s >= 1; s--)
                    keys[s] = u64min(keys[s], u64max(keys[s-1], key));
                keys[0] = u64min(keys[0], key);
            }
        }
        buf ^= 1;
    }

    // --- softmax over exact distances ---
    float w[KSEL];
    int   olin[KSEL];
    float beta = g_beta;
    float d0 = __uint_as_float((unsigned)(keys[0] >> 32));
    float ssum = 0.f;
    #pragma unroll
    for (int i = 0; i < KSEL; i++) {
        float di = __uint_as_float((unsigned)(keys[i] >> 32));
        float wi = expf(beta * (d0 - di));
        w[i] = wi; ssum += wi;
        int o  = (int)(keys[i] & 0xFFFFFFFFULL);
        int oyk = o / WSZ;
        int oxk = o - oyk * WSZ;
        olin[i] = oyk * 64 + oxk;
    }
    float inv = 1.0f / ssum;
    #pragma unroll
    for (int i = 0; i < KSEL; i++) w[i] *= inv;

    // --- weighted patch gather from smem region, plane-major write ---
    float* pd = g_pdeno + ((size_t)t * HH + (ty0 + ly)) * WW + (tx0 + l);
    int base_px = ly * 64 + l;
    #pragma unroll
    for (int dy = 0; dy < PSZ; dy++) {
        #pragma unroll
        for (int dx = 0; dx < PSZ; dx++) {
            float ax = 0.f, ay = 0.f, az = 0.f;
            int bb = base_px + dy * 64 + dx;
            #pragma unroll
            for (int k = 0; k < KSEL; k++) {
                float4 v = reg4[bb + olin[k]];
                ax += w[k] * v.x;
                ay += w[k] * v.y;
                az += w[k] * v.z;
            }
            int p = (dy * PSZ + dx) * 3;
            pd[(size_t)(p + 0) * PLANE] = ax;
            pd[(size_t)(p + 1) * PLANE] = ay;
            pd[(size_t)(p + 2) * PLANE] = az;
        }
    }
}

// ---------------- fold + denormalize ----------------
__global__ void k_fold(float* __restrict__ out) {
    int idx = blockIdx.x * 256 + threadIdx.x;        // over t*c*H*W
    if (idx >= TCNT*CH*HH*WW) return;
    int x = idx & 127;
    int r = idx >> 7;
    int y = r & 127;
    r >>= 7;
    int c = r % 3;
    int t = r / 3;
    float s = 0.f;
    int n = 0;
    #pragma unroll
    for (int py = 0; py < PSZ; py++) {
        int yy = y + 2 - py;
        if (yy < 0 || yy > HH-1) continue;
        #pragma unroll
        for (int px = 0; px < PSZ; px++) {
            int xx = x + 2 - px;
            if (xx < 0 || xx > WW-1) continue;
            int p = (py * PSZ + px) * 3 + c;
            s += g_pdeno[(size_t)p * PLANE + ((size_t)t * HH + yy) * WW + xx];
            n++;
        }
    }
    out[idx] = 127.5f * (s / (float)n + g_mean[t*3+c] + 1.0f);
}

// ---------------- launch ----------------
extern "C" void kernel_launch(void* const* d_in, const int* in_sizes, int n_in,
                              void* d_out, int out_size) {
    const float* noisy = (const float*)d_in[0];
    const int*   sigp  = (const int*)d_in[1];
    float*       out   = (float*)d_out;

    k_means<<<TCNT*CH, 256>>>(noisy, sigp);
    k_xp<<<(TCNT*XPH*XPW + 255)/256, 256>>>(noisy);
    k_ord<<<(NOFF + 255)/256, 256>>>();
    dim3 grid(WW/TX, HH/TY, TCNT);
    k_main<<<grid, 256>>>();
    k_fold<<<(TCNT*CH*HH*WW + 255)/256, 256>>>(out);
}

// round 4
// speedup vs baseline: 1.6956x; 1.6956x over previous
#include <cuda_runtime.h>
#include <math.h>

#define TCNT 4
#define CH 3
#define HH 128
#define WW 128
#define PSZ 5
#define KSEL 14
#define WSZ 29
#define WHALF 14
#define PADT 16
#define XPH 160
#define XPW 160
#define TX 32
#define TY 8
#define NOFF (WSZ*WSZ)
#define DFEAT 75
#define PLANE (TCNT*HH*WW)

// ---------------- device scratch (no allocations allowed) ----------------
__device__ float  g_mean[TCNT*CH];
__device__ float  g_beta;
__device__ float4 g_xp[TCNT*XPH*XPW];          // normalized, mean-sub, reflect-padded; c in .x/.y/.z
__device__ float  g_pdeno[DFEAT*PLANE];        // plane-major [d][t][H][W]
__device__ unsigned short g_ord[NOFF];         // ring-ordered offsets: (oy<<5)|ox

// ---------------- per (t,c) mean + beta ----------------
__global__ void k_means(const float* __restrict__ noisy, const int* __restrict__ sigp) {
    if (blockIdx.x == 0 && threadIdx.x == 0) {
        unsigned bits = *(const unsigned*)sigp;
        float sv = (bits >> 23) ? __uint_as_float(bits) : (float)(int)bits;
        float sig = sv / 127.5f;
        g_beta = 1.0f / (2.0f * sig * sig * (float)DFEAT);
    }
    int b = blockIdx.x;   // t*3+c
    const float* p = noisy + (size_t)b * (HH*WW);
    float s = 0.f;
    for (int i = threadIdx.x; i < HH*WW; i += 256) s += p[i];
    __shared__ float sm[8];
    #pragma unroll
    for (int off = 16; off; off >>= 1) s += __shfl_down_sync(0xffffffffu, s, off);
    if ((threadIdx.x & 31) == 0) sm[threadIdx.x >> 5] = s;
    __syncthreads();
    if (threadIdx.x == 0) {
        float tot = 0.f;
        #pragma unroll
        for (int i = 0; i < 8; i++) tot += sm[i];
        g_mean[b] = tot * (1.0f/(HH*WW)) * (1.0f/127.5f) - 1.0f;
    }
}

// ---------------- build padded normalized image (float4 per pixel) ----------------
__global__ void k_xp(const float* __restrict__ noisy) {
    int idx = blockIdx.x * 256 + threadIdx.x;       // over t*XPH*XPW
    if (idx >= TCNT*XPH*XPW) return;
    int ix = idx % XPW;
    int r  = idx / XPW;
    int iy = r % XPH;
    int t  = r / XPH;
    int jy = iy - PADT; jy = jy < 0 ? -jy : (jy > HH-1 ? 2*(HH-1)-jy : jy);
    int jx = ix - PADT; jx = jx < 0 ? -jx : (jx > WW-1 ? 2*(WW-1)-jx : jx);
    const float* base = noisy + (size_t)t * CH * HH * WW;
    float4 v;
    v.x = base[(size_t)(0*HH+jy)*WW + jx] * (1.f/127.5f) - 1.f - g_mean[t*3+0];
    v.y = base[(size_t)(1*HH+jy)*WW + jx] * (1.f/127.5f) - 1.f - g_mean[t*3+1];
    v.z = base[(size_t)(2*HH+jy)*WW + jx] * (1.f/127.5f) - 1.f - g_mean[t*3+2];
    v.w = 0.f;
    g_xp[idx] = v;
}

// ---------------- ring-order the 841 offsets (center outward) ----------------
__global__ void k_ord() {
    int o = blockIdx.x * blockDim.x + threadIdx.x;
    if (o >= NOFF) return;
    int oy = o / WSZ, ox = o - (o/WSZ)*WSZ;
    int dy = oy - WHALF, dx = ox - WHALF;
    int ady = dy < 0 ? -dy : dy, adx = dx < 0 ? -dx : dx;
    int rr = ady > adx ? ady : adx;
    int before = (rr == 0) ? 0 : (2*rr-1)*(2*rr-1);
    int cnt = 0;
    for (int yy = WHALF - rr; yy < oy; yy++) {
        int a = yy - WHALF; a = a < 0 ? -a : a;
        cnt += (a == rr) ? (2*rr + 1) : 2;
    }
    if (ady == rr) cnt += dx + rr;            // full row: columns before ox
    else          cnt += (dx == rr) ? 1 : 0;  // partial row: only +/- rr columns
    g_ord[before + cnt] = (unsigned short)((oy << 5) | ox);
}

// ---------------- main: distances + top-K + softmax + patch gather ----------------
__global__ void __launch_bounds__(256, 2) k_main() {
    __shared__ float4   reg4[40*64];      // 40KB region
    __shared__ float    e_sm[4][12*36];   // 4 buffers: pair-processed, double-buffered
    __shared__ unsigned ord_sm[NOFF];     // (off_lin<<16) | raster

    int t   = blockIdx.z;
    int ty0 = blockIdx.y * TY;
    int tx0 = blockIdx.x * TX;
    int tid = threadIdx.x;

    // stage region + offset table
    const float4* xp = g_xp + (size_t)t * XPH * XPW;
    #pragma unroll
    for (int i = tid; i < 40*64; i += 256) {
        int r = i >> 6, c = i & 63;
        reg4[i] = xp[(size_t)(ty0 + r) * XPW + tx0 + c];
    }
    for (int i = tid; i < NOFF; i += 256) {
        unsigned p  = g_ord[i];
        unsigned oy = p >> 5, ox = p & 31u;
        ord_sm[i] = ((oy * 64u + ox) << 16) | ((oy * (unsigned)WSZ + ox) & 0x3FFu);
    }
    __syncthreads();

    // register-cached query pixels for the e-plane (slots tid and tid+256)
    int er1 = tid / 36, ec1 = tid - er1 * 36;
    int it2 = tid + 256;
    int er2 = it2 / 36, ec2 = it2 - er2 * 36;       // valid when tid < 176
    float4 q1 = reg4[(er1 + 14) * 64 + (ec1 + 14)];
    float4 q2 = (tid < 176) ? reg4[(er2 + 14) * 64 + (ec2 + 14)] : make_float4(0.f,0.f,0.f,0.f);
    int nb1 = er1 * 64 + ec1;
    int nb2 = er2 * 64 + ec2;

    int ly = tid >> 5, l = tid & 31;

    unsigned keys[KSEL];
    #pragma unroll
    for (int i = 0; i < KSEL; i++) keys[i] = 0xFFFFFFFFu;

    // phase-A fill helper
    auto fillA = [&](float* eb, unsigned ocur) {
        int off_lin = (int)(ocur >> 16);
        float4 n = reg4[nb1 + off_lin];
        float a = q1.x - n.x, b = q1.y - n.y, c = q1.z - n.z;
        eb[tid] = a*a + b*b + c*c;
        if (tid < 176) {
            float4 n2 = reg4[nb2 + off_lin];
            float a2 = q2.x - n2.x, b2 = q2.y - n2.y, c2 = q2.z - n2.z;
            eb[it2] = a2*a2 + b2*b2 + c2*c2;
        }
    };

    // fused vertical+horizontal 5-sum + top-K insert
    auto bc = [&](const float* eb, unsigned ocur) {
        const float* r0 = eb + ly * 36;
        float v_a = r0[l]       + r0[36 + l]   + r0[72 + l]
                  + r0[108 + l] + r0[144 + l];
        int c2 = 32 + (l & 3);
        float v_b = r0[c2]       + r0[36 + c2]  + r0[72 + c2]
                  + r0[108 + c2] + r0[144 + c2];
        float d = v_a;
        #pragma unroll
        for (int k = 1; k <= 4; k++) {
            int src = (l + k) & 31;
            float av = __shfl_sync(0xffffffffu, v_a, src);
            float bv = __shfl_sync(0xffffffffu, v_b, src);
            d += (l + k < 32) ? av : bv;
        }
        unsigned key = (__float_as_uint(d) & 0xFFFFFC00u) | (ocur & 0x3FFu);
        if (__any_sync(0xffffffffu, key < keys[KSEL-1])) {
            #pragma unroll
            for (int s = KSEL-1; s >= 1; s--)
                keys[s] = umin(keys[s], umax(keys[s-1], key));
            keys[0] = umin(keys[0], key);
        }
    };

    // prologue: offsets 0,1 into buffers 0,1
    fillA(e_sm[0], ord_sm[0]);
    fillA(e_sm[1], ord_sm[1]);

    int side = 0;
    for (int i = 0; i < NOFF - 1; i += 2) {
        __syncthreads();
        unsigned c0 = ord_sm[i];
        unsigned c1 = ord_sm[i + 1];
        // fill next pair (pipelined into other side)
        if (i + 2 < NOFF) fillA(e_sm[side ^ 2], ord_sm[i + 2]);
        if (i + 3 < NOFF) fillA(e_sm[(side ^ 2) | 1], ord_sm[i + 3]);
        // reduce current pair (independent chains)
        bc(e_sm[side], c0);
        bc(e_sm[side | 1], c1);
        side ^= 2;
    }
    __syncthreads();
    bc(e_sm[side], ord_sm[NOFF - 1]);   // leftover 841st offset

    // --- softmax over (quantized) distances ---
    float w[KSEL];
    int   olin[KSEL];
    float beta = g_beta;
    float d0 = __uint_as_float(keys[0] & 0xFFFFFC00u);
    float ssum = 0.f;
    #pragma unroll
    for (int i = 0; i < KSEL; i++) {
        float di = __uint_as_float(keys[i] & 0xFFFFFC00u);
        float wi = expf(beta * (d0 - di));
        w[i] = wi; ssum += wi;
        int o  = (int)(keys[i] & 0x3FFu);
        int oyk = o / WSZ;
        int oxk = o - oyk * WSZ;
        olin[i] = oyk * 64 + oxk;
    }
    float inv = 1.0f / ssum;
    #pragma unroll
    for (int i = 0; i < KSEL; i++) w[i] *= inv;

    // --- weighted patch gather from smem region, plane-major write ---
    float* pd = g_pdeno + ((size_t)t * HH + (ty0 + ly)) * WW + (tx0 + l);
    int base_px = ly * 64 + l;
    #pragma unroll
    for (int dy = 0; dy < PSZ; dy++) {
        #pragma unroll
        for (int dx = 0; dx < PSZ; dx++) {
            float ax = 0.f, ay = 0.f, az = 0.f;
            int bb = base_px + dy * 64 + dx;
            #pragma unroll
            for (int k = 0; k < KSEL; k++) {
                float4 v = reg4[bb + olin[k]];
                ax += w[k] * v.x;
                ay += w[k] * v.y;
                az += w[k] * v.z;
            }
            int p = (dy * PSZ + dx) * 3;
            pd[(size_t)(p + 0) * PLANE] = ax;
            pd[(size_t)(p + 1) * PLANE] = ay;
            pd[(size_t)(p + 2) * PLANE] = az;
        }
    }
}

// ---------------- fold + denormalize ----------------
__global__ void k_fold(float* __restrict__ out) {
    int idx = blockIdx.x * 256 + threadIdx.x;        // over t*c*H*W
    if (idx >= TCNT*CH*HH*WW) return;
    int x = idx & 127;
    int r = idx >> 7;
    int y = r & 127;
    r >>= 7;
    int c = r % 3;
    int t = r / 3;
    float s = 0.f;
    int n = 0;
    #pragma unroll
    for (int py = 0; py < PSZ; py++) {
        int yy = y + 2 - py;
        if (yy < 0 || yy > HH-1) continue;
        #pragma unroll
        for (int px = 0; px < PSZ; px++) {
            int xx = x + 2 - px;
            if (xx < 0 || xx > WW-1) continue;
            int p = (py * PSZ + px) * 3 + c;
            s += g_pdeno[(size_t)p * PLANE + ((size_t)t * HH + yy) * WW + xx];
            n++;
        }
    }
    out[idx] = 127.5f * (s / (float)n + g_mean[t*3+c] + 1.0f);
}

// ---------------- launch ----------------
extern "C" void kernel_launch(void* const* d_in, const int* in_sizes, int n_in,
                              void* d_out, int out_size) {
    const float* noisy = (const float*)d_in[0];
    const int*   sigp  = (const int*)d_in[1];
    float*       out   = (float*)d_out;

    k_means<<<TCNT*CH, 256>>>(noisy, sigp);
    k_xp<<<(TCNT*XPH*XPW + 255)/256, 256>>>(noisy);
    k_ord<<<(NOFF + 255)/256, 256>>>();
    dim3 grid(WW/TX, HH/TY, TCNT);
    k_main<<<grid, 256>>>();
    k_fold<<<(TCNT*CH*HH*WW + 255)/256, 256>>>(out);
}

// round 5
// speedup vs baseline: 1.7185x; 1.0135x over previous
#include <cuda_runtime.h>
#include <math.h>

#define TCNT 4
#define CH 3
#define HH 128
#define WW 128
#define PSZ 5
#define KSEL 14
#define WSZ 29
#define WHALF 14
#define PADT 16
#define XPH 160
#define XPW 160
#define TX 32
#define TY 8
#define NOFF (WSZ*WSZ)
#define NPAIR ((NOFF+1)/2)
#define DFEAT 75
#define PLANE (TCNT*HH*WW)

typedef unsigned long long u64;

// ---------------- device scratch (no allocations allowed) ----------------
__device__ float  g_mean[TCNT*CH];
__device__ float  g_beta;
__device__ float4 g_xp[TCNT*XPH*XPW];          // normalized, mean-sub, reflect-padded; c in .x/.y/.z
__device__ float  g_pdeno[DFEAT*PLANE];        // plane-major [d][t][H][W]
__device__ unsigned short g_ord[NOFF];         // ring-ordered offsets: (oy<<5)|ox

__device__ __forceinline__ u64 f2add(u64 a, u64 b) {
    u64 r; asm("add.rn.f32x2 %0,%1,%2;" : "=l"(r) : "l"(a), "l"(b)); return r;
}
__device__ __forceinline__ u64 packf2(float x, float y) {
    return ((u64)__float_as_uint(y) << 32) | (u64)__float_as_uint(x);
}

// ---------------- per (t,c) mean + beta ----------------
__global__ void k_means(const float* __restrict__ noisy, const int* __restrict__ sigp) {
    if (blockIdx.x == 0 && threadIdx.x == 0) {
        unsigned bits = *(const unsigned*)sigp;
        float sv = (bits >> 23) ? __uint_as_float(bits) : (float)(int)bits;
        float sig = sv / 127.5f;
        g_beta = 1.0f / (2.0f * sig * sig * (float)DFEAT);
    }
    int b = blockIdx.x;   // t*3+c
    const float* p = noisy + (size_t)b * (HH*WW);
    float s = 0.f;
    for (int i = threadIdx.x; i < HH*WW; i += 256) s += p[i];
    __shared__ float sm[8];
    #pragma unroll
    for (int off = 16; off; off >>= 1) s += __shfl_down_sync(0xffffffffu, s, off);
    if ((threadIdx.x & 31) == 0) sm[threadIdx.x >> 5] = s;
    __syncthreads();
    if (threadIdx.x == 0) {
        float tot = 0.f;
        #pragma unroll
        for (int i = 0; i < 8; i++) tot += sm[i];
        g_mean[b] = tot * (1.0f/(HH*WW)) * (1.0f/127.5f) - 1.0f;
    }
}

// ---------------- build padded normalized image (float4 per pixel) ----------------
__global__ void k_xp(const float* __restrict__ noisy) {
    int idx = blockIdx.x * 256 + threadIdx.x;       // over t*XPH*XPW
    if (idx >= TCNT*XPH*XPW) return;
    int ix = idx % XPW;
    int r  = idx / XPW;
    int iy = r % XPH;
    int t  = r / XPH;
    int jy = iy - PADT; jy = jy < 0 ? -jy : (jy > HH-1 ? 2*(HH-1)-jy : jy);
    int jx = ix - PADT; jx = jx < 0 ? -jx : (jx > WW-1 ? 2*(WW-1)-jx : jx);
    const float* base = noisy + (size_t)t * CH * HH * WW;
    float4 v;
    v.x = base[(size_t)(0*HH+jy)*WW + jx] * (1.f/127.5f) - 1.f - g_mean[t*3+0];
    v.y = base[(size_t)(1*HH+jy)*WW + jx] * (1.f/127.5f) - 1.f - g_mean[t*3+1];
    v.z = base[(size_t)(2*HH+jy)*WW + jx] * (1.f/127.5f) - 1.f - g_mean[t*3+2];
    v.w = 0.f;
    g_xp[idx] = v;
}

// ---------------- ring-order the 841 offsets (center outward) ----------------
__global__ void k_ord() {
    int o = blockIdx.x * blockDim.x + threadIdx.x;
    if (o >= NOFF) return;
    int oy = o / WSZ, ox = o - (o/WSZ)*WSZ;
    int dy = oy - WHALF, dx = ox - WHALF;
    int ady = dy < 0 ? -dy : dy, adx = dx < 0 ? -dx : dx;
    int rr = ady > adx ? ady : adx;
    int before = (rr == 0) ? 0 : (2*rr-1)*(2*rr-1);
    int cnt = 0;
    for (int yy = WHALF - rr; yy < oy; yy++) {
        int a = yy - WHALF; a = a < 0 ? -a : a;
        cnt += (a == rr) ? (2*rr + 1) : 2;
    }
    if (ady == rr) cnt += dx + rr;            // full row: columns before ox
    else          cnt += (dx == rr) ? 1 : 0;  // partial row: only +/- rr columns
    g_ord[before + cnt] = (unsigned short)((oy << 5) | ox);
}

// ---------------- main: distances + top-K + softmax + patch gather ----------------
__global__ void __launch_bounds__(256, 2) k_main() {
    __shared__ float4   reg4[40*64];        // 40KB region
    __shared__ u64      e_sm[2][12*36];     // double-buffered f32x2 sq-diff planes (pair of offsets)
    __shared__ unsigned ord_sm[2*NPAIR];    // (off_lin<<16) | raster, last slot duplicated

    int t   = blockIdx.z;
    int ty0 = blockIdx.y * TY;
    int tx0 = blockIdx.x * TX;
    int tid = threadIdx.x;

    // stage region + offset table
    const float4* xp = g_xp + (size_t)t * XPH * XPW;
    #pragma unroll
    for (int i = tid; i < 40*64; i += 256) {
        int r = i >> 6, c = i & 63;
        reg4[i] = xp[(size_t)(ty0 + r) * XPW + tx0 + c];
    }
    for (int i = tid; i < 2*NPAIR; i += 256) {
        int j = i < NOFF ? i : NOFF - 1;
        unsigned p  = g_ord[j];
        unsigned oy = p >> 5, ox = p & 31u;
        ord_sm[i] = ((oy * 64u + ox) << 16) | ((oy * (unsigned)WSZ + ox) & 0x3FFu);
    }
    __syncthreads();

    // register-cached query pixels for the e-plane (slots tid and tid+256)
    int er1 = tid / 36, ec1 = tid - er1 * 36;
    int it2 = tid + 256;
    int er2 = it2 / 36, ec2 = it2 - er2 * 36;       // valid when tid < 176
    float4 q1 = reg4[(er1 + 14) * 64 + (ec1 + 14)];
    float4 q2 = (tid < 176) ? reg4[(er2 + 14) * 64 + (ec2 + 14)] : make_float4(0.f,0.f,0.f,0.f);
    int nb1 = er1 * 64 + ec1;
    int nb2 = er2 * 64 + ec2;

    int ly = tid >> 5, l = tid & 31;

    unsigned keys[KSEL];
    #pragma unroll
    for (int i = 0; i < KSEL; i++) keys[i] = 0xFFFFFFFFu;

    // phase-A fill for an offset pair (e stored as f32x2)
    auto fillP = [&](u64* eb, unsigned w0, unsigned w1) {
        int o0 = (int)(w0 >> 16), o1 = (int)(w1 >> 16);
        {
            float4 n0 = reg4[nb1 + o0], n1 = reg4[nb1 + o1];
            float a0 = q1.x - n0.x, b0 = q1.y - n0.y, c0 = q1.z - n0.z;
            float a1 = q1.x - n1.x, b1 = q1.y - n1.y, c1 = q1.z - n1.z;
            eb[tid] = packf2(a0*a0 + b0*b0 + c0*c0, a1*a1 + b1*b1 + c1*c1);
        }
        if (tid < 176) {
            float4 n0 = reg4[nb2 + o0], n1 = reg4[nb2 + o1];
            float a0 = q2.x - n0.x, b0 = q2.y - n0.y, c0 = q2.z - n0.z;
            float a1 = q2.x - n1.x, b1 = q2.y - n1.y, c1 = q2.z - n1.z;
            eb[it2] = packf2(a0*a0 + b0*b0 + c0*c0, a1*a1 + b1*b1 + c1*c1);
        }
    };

    // fused vertical+horizontal 5-sum (both offsets at once) + top-K inserts
    auto bcP = [&](const u64* eb, unsigned w0, unsigned w1, bool kill1) {
        const u64* r0 = eb + ly * 36;
        u64 va = f2add(f2add(f2add(r0[l], r0[36 + l]), f2add(r0[72 + l], r0[108 + l])), r0[144 + l]);
        int c2 = 32 + (l & 3);
        u64 vb = f2add(f2add(f2add(r0[c2], r0[36 + c2]), f2add(r0[72 + c2], r0[108 + c2])), r0[144 + c2]);
        u64 d2 = va;
        #pragma unroll
        for (int k = 1; k <= 4; k++) {
            int src = (l + k) & 31;
            u64 av = __shfl_sync(0xffffffffu, va, src);
            u64 bv = __shfl_sync(0xffffffffu, vb, src);
            d2 = f2add(d2, (l + k < 32) ? av : bv);
        }
        unsigned k0 = ((unsigned)d2 & 0xFFFFFC00u) | (w0 & 0x3FFu);
        unsigned k1 = ((unsigned)(d2 >> 32) & 0xFFFFFC00u) | (w1 & 0x3FFu);
        if (kill1) k1 = 0xFFFFFFFFu;
        if (__any_sync(0xffffffffu, umin(k0, k1) < keys[KSEL-1])) {
            #pragma unroll
            for (int s = KSEL-1; s >= 1; s--)
                keys[s] = umin(keys[s], umax(keys[s-1], k0));
            keys[0] = umin(keys[0], k0);
            #pragma unroll
            for (int s = KSEL-1; s >= 1; s--)
                keys[s] = umin(keys[s], umax(keys[s-1], k1));
            keys[0] = umin(keys[0], k1);
        }
    };

    // prologue: pair 0 into buffer 0
    fillP(e_sm[0], ord_sm[0], ord_sm[1]);

    int side = 0;
    for (int i = 0; i < NPAIR; i++) {
        __syncthreads();
        unsigned w0 = ord_sm[2*i], w1 = ord_sm[2*i + 1];
        if (i + 1 < NPAIR) fillP(e_sm[side ^ 1], ord_sm[2*i + 2], ord_sm[2*i + 3]);
        bcP(e_sm[side], w0, w1, i == NPAIR - 1);   // NOFF odd: last pair duplicates offset
        side ^= 1;
    }

    // --- softmax over (quantized) distances ---
    float w[KSEL];
    int   olin[KSEL];
    float beta = g_beta;
    float d0 = __uint_as_float(keys[0] & 0xFFFFFC00u);
    float ssum = 0.f;
    #pragma unroll
    for (int i = 0; i < KSEL; i++) {
        float di = __uint_as_float(keys[i] & 0xFFFFFC00u);
        float wi = expf(beta * (d0 - di));
        w[i] = wi; ssum += wi;
        int o  = (int)(keys[i] & 0x3FFu);
        int oyk = o / WSZ;
        int oxk = o - oyk * WSZ;
        olin[i] = oyk * 64 + oxk;
    }
    float inv = 1.0f / ssum;
    #pragma unroll
    for (int i = 0; i < KSEL; i++) w[i] *= inv;

    // --- weighted patch gather from smem region, plane-major write ---
    float* pd = g_pdeno + ((size_t)t * HH + (ty0 + ly)) * WW + (tx0 + l);
    int base_px = ly * 64 + l;
    #pragma unroll
    for (int dy = 0; dy < PSZ; dy++) {
        #pragma unroll
        for (int dx = 0; dx < PSZ; dx++) {
            float ax = 0.f, ay = 0.f, az = 0.f;
            int bb = base_px + dy * 64 + dx;
            #pragma unroll
            for (int k = 0; k < KSEL; k++) {
                float4 v = reg4[bb + olin[k]];
                ax += w[k] * v.x;
                ay += w[k] * v.y;
                az += w[k] * v.z;
            }
            int p = (dy * PSZ + dx) * 3;
            pd[(size_t)(p + 0) * PLANE] = ax;
            pd[(size_t)(p + 1) * PLANE] = ay;
            pd[(size_t)(p + 2) * PLANE] = az;
        }
    }
}

// ---------------- fold + denormalize ----------------
__global__ void k_fold(float* __restrict__ out) {
    int idx = blockIdx.x * 256 + threadIdx.x;        // over t*c*H*W
    if (idx >= TCNT*CH*HH*WW) return;
    int x = idx & 127;
    int r = idx >> 7;
    int y = r & 127;
    r >>= 7;
    int c = r % 3;
    int t = r / 3;
    float s = 0.f;
    int n = 0;
    #pragma unroll
    for (int py = 0; py < PSZ; py++) {
        int yy = y + 2 - py;
        if (yy < 0 || yy > HH-1) continue;
        #pragma unroll
        for (int px = 0; px < PSZ; px++) {
            int xx = x + 2 - px;
            if (xx < 0 || xx > WW-1) continue;
            int p = (py * PSZ + px) * 3 + c;
            s += g_pdeno[(size_t)p * PLANE + ((size_t)t * HH + yy) * WW + xx];
            n++;
        }
    }
    out[idx] = 127.5f * (s / (float)n + g_mean[t*3+c] + 1.0f);
}

// ---------------- launch ----------------
extern "C" void kernel_launch(void* const* d_in, const int* in_sizes, int n_in,
                              void* d_out, int out_size) {
    const float* noisy = (const float*)d_in[0];
    const int*   sigp  = (const int*)d_in[1];
    float*       out   = (float*)d_out;

    k_means<<<TCNT*CH, 256>>>(noisy, sigp);
    k_xp<<<(TCNT*XPH*XPW + 255)/256, 256>>>(noisy);
    k_ord<<<(NOFF + 255)/256, 256>>>();
    dim3 grid(WW/TX, HH/TY, TCNT);
    k_main<<<grid, 256>>>();
    k_fold<<<(TCNT*CH*HH*WW + 255)/256, 256>>>(out);
}